// round 1
// baseline (speedup 1.0000x reference)
#include <cuda_runtime.h>

// Adder2D: out[n,co,h,w] = -sum_{ci,kh,kw} |x_pad[n,ci,h+kh-1,w+kw-1] - w[co,ci,kh,kw]|
// x: [16,64,32,32] f32, w: [64,64,3,3] f32, out: [16,64,32,32] f32
// NOTE: zero padding CONTRIBUTES here (|0 - w| != 0), so halo must be exact zeros.

#define CI_   64
#define CO_   64
#define H_    32
#define W_    32

#define CO_T     8     // co per block
#define TILE_H   16    // output rows per block
#define CI_CHUNK 4     // ci staged in smem per sync
#define THREADS  128

#define XS_ROWS (TILE_H + 2)   // 18
#define XS_COLS (W_ + 2)       // 34

__device__ __forceinline__ unsigned long long f2add(unsigned long long a, unsigned long long b) {
    unsigned long long r;
    asm("add.rn.f32x2 %0, %1, %2;" : "=l"(r) : "l"(a), "l"(b));
    return r;
}

__device__ __forceinline__ unsigned long long packff(float lo, float hi) {
    unsigned long long r;
    asm("mov.b64 %0, {%1, %2};" : "=l"(r) : "f"(lo), "f"(hi));
    return r;
}

__global__ void __launch_bounds__(THREADS)
adder2d_kernel(const float* __restrict__ x,
               const float* __restrict__ w,
               float* __restrict__ out)
{
    // x tile (with halo) for CI_CHUNK channels
    __shared__ float xs[CI_CHUNK][XS_ROWS][XS_COLS];
    // w, pre-negated and duplicated into both halves of a 64b word:
    // ws2[co_local * (CI_*9) + ci*9 + kh*3 + kw] = pack(-w, -w)
    __shared__ unsigned long long ws2[CO_T * CI_ * 9];

    const int tid = threadIdx.x;
    const int h0  = blockIdx.x * TILE_H;
    const int co0 = blockIdx.y * CO_T;
    const int n   = blockIdx.z;

    // ---- load w for this co block (once), negated + duplicated ----
    for (int i = tid; i < CO_T * CI_ * 9; i += THREADS) {
        const int c = i / (CI_ * 9);
        const int j = i - c * (CI_ * 9);
        const float wv = w[(co0 + c) * (CI_ * 9) + j];
        const unsigned int b = __float_as_uint(-wv);
        ws2[i] = ((unsigned long long)b << 32) | (unsigned long long)b;
    }

    // ---- accumulators: 8 co x 2 pixel-pairs (pairs = rows {py,py+4} and {py+8,py+12}) ----
    unsigned long long acc[CO_T][2];
    #pragma unroll
    for (int c = 0; c < CO_T; ++c) { acc[c][0] = 0ull; acc[c][1] = 0ull; }

    const int px = tid & 31;   // output column
    const int py = tid >> 5;   // 0..3; this thread owns rows py, py+4, py+8, py+12 of the tile

    const float* xn = x + (size_t)n * (CI_ * H_ * W_);

    for (int cc = 0; cc < CI_; cc += CI_CHUNK) {
        __syncthreads();  // protect previous chunk's reads before overwrite
        // ---- stage x[cc .. cc+3] tile with zero halo ----
        for (int i = tid; i < CI_CHUNK * XS_ROWS * XS_COLS; i += THREADS) {
            const int cl = i / (XS_ROWS * XS_COLS);
            const int r  = (i / XS_COLS) % XS_ROWS;
            const int c2 = i % XS_COLS;
            const int gh = h0 + r - 1;
            const int gw = c2 - 1;
            float v = 0.0f;
            if ((unsigned)gh < (unsigned)H_ && (unsigned)gw < (unsigned)W_)
                v = xn[(cc + cl) * (H_ * W_) + gh * W_ + gw];
            (&xs[0][0][0])[i] = v;
        }
        __syncthreads();

        #pragma unroll 1
        for (int cl = 0; cl < CI_CHUNK; ++cl) {
            const unsigned long long* wrow = &ws2[(cc + cl) * 9];
            #pragma unroll
            for (int kh = 0; kh < 3; ++kh) {
                #pragma unroll
                for (int kw = 0; kw < 3; ++kw) {
                    const float xv0 = xs[cl][py + 0  + kh][px + kw];
                    const float xv1 = xs[cl][py + 4  + kh][px + kw];
                    const float xv2 = xs[cl][py + 8  + kh][px + kw];
                    const float xv3 = xs[cl][py + 12 + kh][px + kw];
                    const unsigned long long x01 = packff(xv0, xv1);
                    const unsigned long long x23 = packff(xv2, xv3);
                    const int tap = kh * 3 + kw;
                    #pragma unroll
                    for (int c = 0; c < CO_T; ++c) {
                        const unsigned long long w2 = wrow[c * (CI_ * 9) + tap];
                        unsigned long long d0 = f2add(x01, w2);      // x - w (fma pipe)
                        unsigned long long d1 = f2add(x23, w2);
                        d0 &= 0x7fffffff7fffffffULL;                 // |.| (alu pipe, 2x LOP3)
                        d1 &= 0x7fffffff7fffffffULL;
                        acc[c][0] = f2add(acc[c][0], d0);            // accumulate (fma pipe)
                        acc[c][1] = f2add(acc[c][1], d1);
                    }
                }
            }
        }
    }

    // ---- epilogue: out = -acc, coalesced along px ----
    #pragma unroll
    for (int c = 0; c < CO_T; ++c) {
        const float a0 = __uint_as_float((unsigned int)(acc[c][0] & 0xffffffffu)); // row py
        const float a1 = __uint_as_float((unsigned int)(acc[c][0] >> 32));         // row py+4
        const float a2 = __uint_as_float((unsigned int)(acc[c][1] & 0xffffffffu)); // row py+8
        const float a3 = __uint_as_float((unsigned int)(acc[c][1] >> 32));         // row py+12
        float* ob = out + (((size_t)n * CO_ + (co0 + c)) * H_) * W_;
        ob[(h0 + py + 0 ) * W_ + px] = -a0;
        ob[(h0 + py + 4 ) * W_ + px] = -a1;
        ob[(h0 + py + 8 ) * W_ + px] = -a2;
        ob[(h0 + py + 12) * W_ + px] = -a3;
    }
}

extern "C" void kernel_launch(void* const* d_in, const int* in_sizes, int n_in,
                              void* d_out, int out_size)
{
    const float* x = (const float*)d_in[0];
    const float* w = (const float*)d_in[1];
    float* out = (float*)d_out;

    const int N = in_sizes[0] / (CI_ * H_ * W_);   // 16

    dim3 grid(H_ / TILE_H, CO_ / CO_T, N);         // (2, 8, 16) = 256 blocks
    adder2d_kernel<<<grid, THREADS>>>(x, w, out);
}

// round 2
// speedup vs baseline: 1.1883x; 1.1883x over previous
#include <cuda_runtime.h>

// Adder2D: out[n,co,h,w] = -sum_{ci,kh,kw} |x_pad[n,ci,h+kh-1,w+kw-1] - w[co,ci,kh,kw]|
// x: [16,64,32,32] f32, w: [64,64,3,3] f32, out: [16,64,32,32] f32
// Zero padding CONTRIBUTES (|0 - w| != 0) -> halo must be exact zeros.
//
// R2 design: occupancy-first. 2048 small blocks (TILE_H=8, CO_T=4, 128 thr),
// co-packed f32x2 math: diff on fma pipe (FADD2), abs on alu pipe (LOP3),
// accumulate on fma pipe. ~44 warps/SM resident vs 6.7 in R1.

#define CI_   64
#define CO_   64
#define H_    32
#define W_    32

#define CO_T     4     // co per block (2 packed pairs)
#define C2_      (CO_T/2)
#define TILE_H   8     // output rows per block
#define CI_CHUNK 8     // ci staged in smem per sync
#define THREADS  128

#define XS_ROWS (TILE_H + 2)   // 10
#define XS_COLS (W_ + 2)       // 34

__device__ __forceinline__ unsigned long long f2add(unsigned long long a, unsigned long long b) {
    unsigned long long r;
    asm("add.rn.f32x2 %0, %1, %2;" : "=l"(r) : "l"(a), "l"(b));
    return r;
}

__device__ __forceinline__ unsigned long long packff(float lo, float hi) {
    unsigned long long r;
    asm("mov.b64 %0, {%1, %2};" : "=l"(r) : "f"(lo), "f"(hi));
    return r;
}

__global__ void __launch_bounds__(THREADS)
adder2d_kernel(const float* __restrict__ x,
               const float* __restrict__ w,
               float* __restrict__ out)
{
    // x tile (with halo) for CI_CHUNK channels
    __shared__ float xs[CI_CHUNK][XS_ROWS][XS_COLS];
    // co-pair packed negated weights: ws2[c2*(CI_*9) + ci*9 + tap] = pack(-w[co0+2c2], -w[co0+2c2+1])
    __shared__ unsigned long long ws2[C2_ * CI_ * 9];

    const int tid = threadIdx.x;
    const int h0  = blockIdx.x * TILE_H;
    const int co0 = blockIdx.y * CO_T;
    const int n   = blockIdx.z;

    // ---- stage w for this co block (once), negated + co-pair packed ----
    for (int i = tid; i < C2_ * CI_ * 9; i += THREADS) {
        const int c2 = i / (CI_ * 9);
        const int j  = i - c2 * (CI_ * 9);
        const float w0 = w[(co0 + 2 * c2 + 0) * (CI_ * 9) + j];
        const float w1 = w[(co0 + 2 * c2 + 1) * (CI_ * 9) + j];
        ws2[i] = packff(-w0, -w1);
    }

    // ---- accumulators: 2 pixels x 2 co-pairs ----
    unsigned long long acc[2][C2_];
    #pragma unroll
    for (int p = 0; p < 2; ++p)
        #pragma unroll
        for (int c2 = 0; c2 < C2_; ++c2) acc[p][c2] = 0ull;

    const int px = tid & 31;   // output column
    const int py = tid >> 5;   // 0..3; this thread owns rows py and py+4

    const float* xn = x + (size_t)n * (CI_ * H_ * W_);

    for (int cc = 0; cc < CI_; cc += CI_CHUNK) {
        __syncthreads();  // protect previous chunk's reads before overwrite
        // ---- stage x[cc .. cc+CI_CHUNK-1] tile with zero halo ----
        for (int i = tid; i < CI_CHUNK * XS_ROWS * XS_COLS; i += THREADS) {
            const int cl = i / (XS_ROWS * XS_COLS);
            const int r  = (i / XS_COLS) % XS_ROWS;
            const int c  = i % XS_COLS;
            const int gh = h0 + r - 1;
            const int gw = c - 1;
            float v = 0.0f;
            if ((unsigned)gh < (unsigned)H_ && (unsigned)gw < (unsigned)W_)
                v = xn[(cc + cl) * (H_ * W_) + gh * W_ + gw];
            (&xs[0][0][0])[i] = v;
        }
        __syncthreads();

        #pragma unroll 1
        for (int cl = 0; cl < CI_CHUNK; ++cl) {
            const unsigned long long* wrow = &ws2[(cc + cl) * 9];
            #pragma unroll
            for (int kh = 0; kh < 3; ++kh) {
                #pragma unroll
                for (int kw = 0; kw < 3; ++kw) {
                    const float a0 = xs[cl][py + 0 + kh][px + kw];
                    const float a1 = xs[cl][py + 4 + kh][px + kw];
                    const unsigned long long x0 = packff(a0, a0);
                    const unsigned long long x1 = packff(a1, a1);
                    const int tap = kh * 3 + kw;
                    #pragma unroll
                    for (int c2 = 0; c2 < C2_; ++c2) {
                        const unsigned long long w2 = wrow[c2 * (CI_ * 9) + tap];
                        unsigned long long d0 = f2add(x0, w2);      // x - w       (fma pipe)
                        unsigned long long d1 = f2add(x1, w2);
                        d0 &= 0x7fffffff7fffffffULL;                // |.|         (alu pipe)
                        d1 &= 0x7fffffff7fffffffULL;
                        acc[0][c2] = f2add(acc[0][c2], d0);          // accumulate  (fma pipe)
                        acc[1][c2] = f2add(acc[1][c2], d1);
                    }
                }
            }
        }
    }

    // ---- epilogue: out = -acc (lo -> co0+2c2, hi -> co0+2c2+1), coalesced along px ----
    #pragma unroll
    for (int c2 = 0; c2 < C2_; ++c2) {
        #pragma unroll
        for (int p = 0; p < 2; ++p) {
            const float lo = __uint_as_float((unsigned int)(acc[p][c2] & 0xffffffffu));
            const float hi = __uint_as_float((unsigned int)(acc[p][c2] >> 32));
            const int h = h0 + py + 4 * p;
            out[(((size_t)n * CO_ + (co0 + 2 * c2 + 0)) * H_ + h) * W_ + px] = -lo;
            out[(((size_t)n * CO_ + (co0 + 2 * c2 + 1)) * H_ + h) * W_ + px] = -hi;
        }
    }
}

extern "C" void kernel_launch(void* const* d_in, const int* in_sizes, int n_in,
                              void* d_out, int out_size)
{
    const float* x = (const float*)d_in[0];
    const float* w = (const float*)d_in[1];
    float* out = (float*)d_out;

    const int N = in_sizes[0] / (CI_ * H_ * W_);   // 16

    dim3 grid(H_ / TILE_H, CO_ / CO_T, N);         // (4, 16, 16) = 2048 blocks
    adder2d_kernel<<<grid, THREADS>>>(x, w, out);
}

// round 3
// speedup vs baseline: 1.3254x; 1.1154x over previous
#include <cuda_runtime.h>

// Adder2D: out[n,co,h,w] = -sum_{ci,kh,kw} |x_pad[n,ci,h+kh-1,w+kw-1] - w[co,ci,kh,kw]|
// x: [16,64,32,32] f32, w: [64,64,3,3] f32, out: [16,64,32,32] f32
// Zero padding CONTRIBUTES (|0 - w| != 0) -> halo must be exact zeros.
//
// R3: ci-split x2 across blocks (grid 2048, atomicAdd combine after async memset)
// + x stored pre-duplicated as 64-bit in smem (LDS.64, no packing MOVs).
// Core math: FADD2 diff (fma pipe) -> 64-bit sign-AND (alu pipe) -> FADD2 acc (fma pipe).

#define CI_   64
#define CO_   64
#define H_    32
#define W_    32

#define CO_T     4     // co per block (2 packed pairs)
#define C2_      (CO_T/2)
#define TILE_H   8     // output rows per block
#define CI_HALF  32    // ci handled per block (reduction split x2)
#define CI_CHUNK 4     // ci staged in smem per sync
#define THREADS  128

#define XS_ROWS (TILE_H + 2)   // 10
#define XS_COLS (W_ + 2)       // 34

typedef unsigned long long u64;

__device__ __forceinline__ u64 f2add(u64 a, u64 b) {
    u64 r;
    asm("add.rn.f32x2 %0, %1, %2;" : "=l"(r) : "l"(a), "l"(b));
    return r;
}

__device__ __forceinline__ u64 packff(float lo, float hi) {
    u64 r;
    asm("mov.b64 %0, {%1, %2};" : "=l"(r) : "f"(lo), "f"(hi));
    return r;
}

__global__ void __launch_bounds__(THREADS, 12)
adder2d_kernel(const float* __restrict__ x,
               const float* __restrict__ w,
               float* __restrict__ out)
{
    // x tile (with halo), each value duplicated into both halves of a u64
    __shared__ u64 xs2[CI_CHUNK][XS_ROWS][XS_COLS];
    // co-pair packed negated weights for this block's ci half
    __shared__ u64 ws2[C2_][CI_HALF][9];

    const int tid = threadIdx.x;
    const int h0  = blockIdx.x * TILE_H;
    const int co0 = blockIdx.y * CO_T;
    const int n   = blockIdx.z >> 1;
    const int ci0 = (blockIdx.z & 1) * CI_HALF;

    // ---- stage w (once): negated + co-pair packed ----
    for (int i = tid; i < C2_ * CI_HALF * 9; i += THREADS) {
        const int c2  = i / (CI_HALF * 9);
        const int j   = i - c2 * (CI_HALF * 9);
        const int cil = j / 9;
        const int tap = j - cil * 9;
        const float w0 = w[(co0 + 2 * c2 + 0) * (CI_ * 9) + (ci0 + cil) * 9 + tap];
        const float w1 = w[(co0 + 2 * c2 + 1) * (CI_ * 9) + (ci0 + cil) * 9 + tap];
        (&ws2[0][0][0])[i] = packff(-w0, -w1);
    }

    // accumulators: 2 pixels x 2 co-pairs
    u64 acc[2][C2_];
    #pragma unroll
    for (int p = 0; p < 2; ++p)
        #pragma unroll
        for (int c2 = 0; c2 < C2_; ++c2) acc[p][c2] = 0ull;

    const int px = tid & 31;   // output column
    const int py = tid >> 5;   // 0..3; owns rows py and py+4 of the tile

    const float* xn = x + (size_t)n * (CI_ * H_ * W_) + (size_t)ci0 * (H_ * W_);

    for (int cc = 0; cc < CI_HALF; cc += CI_CHUNK) {
        __syncthreads();  // protect previous chunk's reads before overwrite
        // ---- stage x chunk, duplicated, with exact-zero halo ----
        for (int i = tid; i < CI_CHUNK * XS_ROWS * XS_COLS; i += THREADS) {
            const int cl = i / (XS_ROWS * XS_COLS);
            const int r  = (i / XS_COLS) % XS_ROWS;
            const int c  = i % XS_COLS;
            const int gh = h0 + r - 1;
            const int gw = c - 1;
            float v = 0.0f;
            if ((unsigned)gh < (unsigned)H_ && (unsigned)gw < (unsigned)W_)
                v = xn[(cc + cl) * (H_ * W_) + gh * W_ + gw];
            (&xs2[0][0][0])[i] = packff(v, v);
        }
        __syncthreads();

        #pragma unroll 1
        for (int cl = 0; cl < CI_CHUNK; ++cl) {
            const u64* wr0 = &ws2[0][cc + cl][0];
            const u64* wr1 = &ws2[1][cc + cl][0];
            #pragma unroll
            for (int kh = 0; kh < 3; ++kh) {
                #pragma unroll
                for (int kw = 0; kw < 3; ++kw) {
                    const u64 x0 = xs2[cl][py + 0 + kh][px + kw];  // pixel row py
                    const u64 x1 = xs2[cl][py + 4 + kh][px + kw];  // pixel row py+4
                    const int tap = kh * 3 + kw;
                    const u64 wa = wr0[tap];
                    const u64 wb = wr1[tap];
                    u64 d00 = f2add(x0, wa);             // fma pipe
                    u64 d10 = f2add(x1, wa);
                    u64 d01 = f2add(x0, wb);
                    u64 d11 = f2add(x1, wb);
                    d00 &= 0x7fffffff7fffffffULL;        // alu pipe (2x LOP3 each)
                    d10 &= 0x7fffffff7fffffffULL;
                    d01 &= 0x7fffffff7fffffffULL;
                    d11 &= 0x7fffffff7fffffffULL;
                    acc[0][0] = f2add(acc[0][0], d00);   // fma pipe
                    acc[1][0] = f2add(acc[1][0], d10);
                    acc[0][1] = f2add(acc[0][1], d01);
                    acc[1][1] = f2add(acc[1][1], d11);
                }
            }
        }
    }

    // ---- epilogue: combine the two ci-halves via atomicAdd (out pre-zeroed) ----
    #pragma unroll
    for (int c2 = 0; c2 < C2_; ++c2) {
        #pragma unroll
        for (int p = 0; p < 2; ++p) {
            const float lo = __uint_as_float((unsigned int)(acc[p][c2] & 0xffffffffu));
            const float hi = __uint_as_float((unsigned int)(acc[p][c2] >> 32));
            const int h = h0 + py + 4 * p;
            atomicAdd(&out[(((size_t)n * CO_ + (co0 + 2 * c2 + 0)) * H_ + h) * W_ + px], -lo);
            atomicAdd(&out[(((size_t)n * CO_ + (co0 + 2 * c2 + 1)) * H_ + h) * W_ + px], -hi);
        }
    }
}

extern "C" void kernel_launch(void* const* d_in, const int* in_sizes, int n_in,
                              void* d_out, int out_size)
{
    const float* x = (const float*)d_in[0];
    const float* w = (const float*)d_in[1];
    float* out = (float*)d_out;

    const int N = in_sizes[0] / (CI_ * H_ * W_);   // 16

    // zero the output (graph-capturable memset node); atomics accumulate into it
    cudaMemsetAsync(d_out, 0, (size_t)out_size * sizeof(float));

    dim3 grid(H_ / TILE_H, CO_ / CO_T, N * 2);     // (4, 16, 32) = 2048 blocks
    adder2d_kernel<<<grid, THREADS>>>(x, w, out);
}

// round 6
// speedup vs baseline: 1.6836x; 1.2703x over previous
#include <cuda_runtime.h>

// Adder2D: out[n,co,h,w] = -sum_{ci,kh,kw} |x_pad - w|
// Math per packed co-pair: FADD2 diff (fma) -> 64-bit sign-AND (2x LOP3, alu) -> FADD2 acc (fma).
// R6: stage the block's entire ci-slice ONCE (2 barriers/block total), CO_T=8 for w amortization,
// ci-split x8 across blocks (atomicAdd combine), 4096 blocks for tail granularity.

#define CI_   64
#define CO_   64
#define H_    32
#define W_    32

#define CO_T     8     // co per block -> 4 packed pairs
#define C2_      (CO_T/2)
#define TILE_H   8     // output rows per block (thread owns rows py, py+4)
#define CI_Q     8     // ci per block (reduction split x8)
#define THREADS  128

#define XS_ROWS (TILE_H + 2)   // 10
#define XS_COLS (W_ + 2)       // 34

typedef unsigned long long u64;

__device__ __forceinline__ u64 f2add(u64 a, u64 b) {
    u64 r;
    asm("add.rn.f32x2 %0, %1, %2;" : "=l"(r) : "l"(a), "l"(b));
    return r;
}

__device__ __forceinline__ u64 packff(float lo, float hi) {
    u64 r;
    asm("mov.b64 %0, {%1, %2};" : "=l"(r) : "f"(lo), "f"(hi));
    return r;
}

__device__ __forceinline__ float u64lo(u64 v) {
    return __uint_as_float((unsigned int)(v & 0xffffffffu));
}
__device__ __forceinline__ float u64hi(u64 v) {
    return __uint_as_float((unsigned int)(v >> 32));
}

__global__ void __launch_bounds__(THREADS, 9)
adder2d_kernel(const float* __restrict__ x,
               const float* __restrict__ w,
               float* __restrict__ out)
{
    // whole ci-slice x tile (halo incl.), each value duplicated in a u64: 21.8KB
    __shared__ u64 xs2[CI_Q][XS_ROWS][XS_COLS];
    // co-pair packed negated weights: 2.3KB
    __shared__ u64 ws2[C2_][CI_Q][9];

    const int tid = threadIdx.x;
    const int h0  = blockIdx.x * TILE_H;
    const int co0 = blockIdx.y * CO_T;
    const int n   = blockIdx.z >> 3;
    const int ci0 = (blockIdx.z & 7) * CI_Q;

    // ---- stage w: negated + co-pair packed ----
    for (int i = tid; i < C2_ * CI_Q * 9; i += THREADS) {
        const int c2  = i / (CI_Q * 9);
        const int j   = i - c2 * (CI_Q * 9);
        const int cil = j / 9;
        const int tap = j - cil * 9;
        const float w0 = w[(co0 + 2 * c2 + 0) * (CI_ * 9) + (ci0 + cil) * 9 + tap];
        const float w1 = w[(co0 + 2 * c2 + 1) * (CI_ * 9) + (ci0 + cil) * 9 + tap];
        (&ws2[0][0][0])[i] = packff(-w0, -w1);
    }

    // ---- stage entire x slice (duplicated), exact-zero halo ----
    const float* xn = x + (size_t)n * (CI_ * H_ * W_) + (size_t)ci0 * (H_ * W_);
    for (int i = tid; i < CI_Q * XS_ROWS * XS_COLS; i += THREADS) {
        const int cl = i / (XS_ROWS * XS_COLS);
        const int r  = (i / XS_COLS) % XS_ROWS;
        const int c  = i % XS_COLS;
        const int gh = h0 + r - 1;
        const int gw = c - 1;
        float v = 0.0f;
        if ((unsigned)gh < (unsigned)H_ && (unsigned)gw < (unsigned)W_)
            v = xn[cl * (H_ * W_) + gh * W_ + gw];
        (&xs2[0][0][0])[i] = packff(v, v);
    }
    __syncthreads();

    // accumulators: [pixel(2)][co-pair(4)]
    u64 acc[2][C2_];
    #pragma unroll
    for (int p = 0; p < 2; ++p)
        #pragma unroll
        for (int c2 = 0; c2 < C2_; ++c2) acc[p][c2] = 0ull;

    const int px = tid & 31;   // output column
    const int py = tid >> 5;   // 0..3; owns rows py and py+4

    #pragma unroll 2
    for (int cl = 0; cl < CI_Q; ++cl) {
        #pragma unroll
        for (int kh = 0; kh < 3; ++kh) {
            #pragma unroll
            for (int kw = 0; kw < 3; ++kw) {
                const u64 x0 = xs2[cl][py + 0 + kh][px + kw];   // LDS.64
                const u64 x1 = xs2[cl][py + 4 + kh][px + kw];   // LDS.64
                const int tap = kh * 3 + kw;
                #pragma unroll
                for (int c2 = 0; c2 < C2_; ++c2) {
                    const u64 w2 = ws2[c2][cl][tap];            // LDS.64 (uniform bcast)
                    u64 d0 = f2add(x0, w2);                     // fma pipe
                    u64 d1 = f2add(x1, w2);
                    d0 &= 0x7fffffff7fffffffULL;                // alu pipe (2x LOP3)
                    d1 &= 0x7fffffff7fffffffULL;
                    acc[0][c2] = f2add(acc[0][c2], d0);          // fma pipe
                    acc[1][c2] = f2add(acc[1][c2], d1);
                }
            }
        }
    }

    // ---- epilogue: combine ci-slices via atomicAdd (out pre-zeroed) ----
    #pragma unroll
    for (int c2 = 0; c2 < C2_; ++c2) {
        #pragma unroll
        for (int p = 0; p < 2; ++p) {
            const float lo = u64lo(acc[p][c2]);
            const float hi = u64hi(acc[p][c2]);
            const int h = h0 + py + 4 * p;
            atomicAdd(&out[(((size_t)n * CO_ + (co0 + 2 * c2 + 0)) * H_ + h) * W_ + px], -lo);
            atomicAdd(&out[(((size_t)n * CO_ + (co0 + 2 * c2 + 1)) * H_ + h) * W_ + px], -hi);
        }
    }
}

extern "C" void kernel_launch(void* const* d_in, const int* in_sizes, int n_in,
                              void* d_out, int out_size)
{
    const float* x = (const float*)d_in[0];
    const float* w = (const float*)d_in[1];
    float* out = (float*)d_out;

    const int N = in_sizes[0] / (CI_ * H_ * W_);   // 16

    cudaMemsetAsync(d_out, 0, (size_t)out_size * sizeof(float));

    dim3 grid(H_ / TILE_H, CO_ / CO_T, N * 8);     // (4, 8, 128) = 4096 blocks
    adder2d_kernel<<<grid, THREADS>>>(x, w, out);
}